// round 11
// baseline (speedup 1.0000x reference)
#include <cuda_runtime.h>

// ============================================================================
// Problem constants
// ============================================================================
#define NFEAT 32
#define MAX_ATOMS 10000
#define NPATHS 19

// Scratch: per-atom B = A @ W1 (+0.5*b1 on m=0 rows)
__device__ float g_B[MAX_ATOMS * 9 * NFEAT];

// ============================================================================
// constexpr math (compile-time): factorial, sqrt, exp
// ============================================================================
__host__ __device__ constexpr double cfact(int n) {
    double r = 1.0;
    for (int i = 2; i <= n; ++i) r *= (double)i;
    return r;
}
__host__ __device__ constexpr double csqrt_(double x) {
    if (x <= 0.0) return 0.0;
    double g = x < 1.0 ? 1.0 : x;
    for (int i = 0; i < 80; ++i) g = 0.5 * (g + x / g);
    return g;
}
__host__ __device__ constexpr double cexp_(double x) {
    double y = x * (1.0 / 1024.0);
    double s = 1.0 + y + y * y / 2.0 + y * y * y / 6.0 + y * y * y * y / 24.0 +
               y * y * y * y * y / 120.0 + y * y * y * y * y * y / 720.0;
    for (int i = 0; i < 10; ++i) s = s * s;
    return s;
}
__host__ __device__ constexpr int iabs_(int x) { return x < 0 ? -x : x; }

// ============================================================================
// constexpr Clebsch-Gordan machinery — bit-faithful port of the reference
// ============================================================================
__host__ __device__ constexpr double cg_c(int j1, int m1, int j2, int m2, int j3, int m3) {
    if (m1 + m2 != m3) return 0.0;
    if (j3 < iabs_(j1 - j2) || j3 > j1 + j2) return 0.0;
    if (iabs_(m1) > j1 || iabs_(m2) > j2 || iabs_(m3) > j3) return 0.0;
    double pref = csqrt_((2.0 * j3 + 1.0) * cfact(j3 + j1 - j2) * cfact(j3 - j1 + j2) *
                         cfact(j1 + j2 - j3) / cfact(j1 + j2 + j3 + 1));
    pref *= csqrt_(cfact(j3 + m3) * cfact(j3 - m3) * cfact(j1 - m1) * cfact(j1 + m1) *
                   cfact(j2 - m2) * cfact(j2 + m2));
    double s = 0.0;
    for (int k = 0; k <= j1 + j2 - j3; ++k) {
        int d1 = j1 + j2 - j3 - k, d2 = j1 - m1 - k, d3 = j2 + m2 - k;
        int d4 = j3 - j2 + m1 + k, d5 = j3 - j1 - m2 + k;
        if (d1 < 0 || d2 < 0 || d3 < 0 || d4 < 0 || d5 < 0) continue;
        double den = cfact(k) * cfact(d1) * cfact(d2) * cfact(d3) * cfact(d4) * cfact(d5);
        s += ((k & 1) ? -1.0 : 1.0) / den;
    }
    return pref * s;
}

struct CPX { double re, im; };
__host__ __device__ constexpr CPX cmulc(CPX a, CPX b) {
    return CPX{a.re * b.re - a.im * b.im, a.re * b.im + a.im * b.re};
}
__host__ __device__ constexpr CPX Uent(int l, int mr, int mc) {
    (void)l;
    double is2 = 1.0 / csqrt_(2.0);
    if (mr > 0) {
        if (mc == mr)  return CPX{((mr & 1) ? -1.0 : 1.0) * is2, 0.0};
        if (mc == -mr) return CPX{is2, 0.0};
    } else if (mr == 0) {
        if (mc == 0) return CPX{1.0, 0.0};
    } else {
        int mu = -mr;
        if (mc == mr) return CPX{0.0, is2};
        if (mc == mu) return CPX{0.0, -((mu & 1) ? -1.0 : 1.0) * is2};
    }
    return CPX{0.0, 0.0};
}

__host__ __device__ constexpr double real_cg(int l1, int l2, int l3, int a, int b, int c) {
    int m1 = a - l1, m2 = b - l2, m3 = c - l3;
    double re = 0.0, im = 0.0;
    for (int sx = 0; sx < 2; ++sx) {
        if (sx && m1 == 0) continue;
        int x = sx ? -m1 : m1;
        CPX u1 = Uent(l1, m1, x); u1.im = -u1.im;
        for (int sy = 0; sy < 2; ++sy) {
            if (sy && m2 == 0) continue;
            int y = sy ? -m2 : m2;
            CPX u2 = Uent(l2, m2, y); u2.im = -u2.im;
            for (int sz = 0; sz < 2; ++sz) {
                if (sz && m3 == 0) continue;
                int z = sz ? -m3 : m3;
                CPX u3 = Uent(l3, m3, z);
                double cg = cg_c(l1, x, l2, y, l3, z);
                if (cg == 0.0) continue;
                CPX t = cmulc(cmulc(u1, u2), u3);
                re += t.re * cg;
                im += t.im * cg;
            }
        }
    }
    return ((l1 + l2 + l3) & 1) ? im : re;
}

// Path table, same enumeration order as reference _build_paths()
__host__ __device__ constexpr int PL1[NPATHS] = {0,0,0,1,1,1,1,1,1,1,2,2,2,2,2,2,2,2,2};
__host__ __device__ constexpr int PL2[NPATHS] = {0,1,2,0,1,1,1,2,2,2,0,1,1,1,2,2,2,2,2};
__host__ __device__ constexpr int PL3[NPATHS] = {0,1,2,1,0,1,2,1,2,3,2,1,2,3,0,1,2,3,4};

template <int I> struct IC { static constexpr int v = I; };
template <int I, int N, class F>
__device__ __forceinline__ void sfor(F&& f) {
    if constexpr (I < N) {
        f(IC<I>{});
        sfor<I + 1, N>(f);
    }
}

__device__ __forceinline__ float wsum(float v) {
    v += __shfl_xor_sync(0xffffffffu, v, 16);
    v += __shfl_xor_sync(0xffffffffu, v, 8);
    v += __shfl_xor_sync(0xffffffffu, v, 4);
    v += __shfl_xor_sync(0xffffffffu, v, 2);
    v += __shfl_xor_sync(0xffffffffu, v, 1);
    return v;
}

// packed f32x2 fma (sm_103): acc = a*b + acc, lanes independent
__device__ __forceinline__ void ffma2(unsigned long long& acc,
                                      unsigned long long a, unsigned long long b) {
    asm("fma.rn.f32x2 %0, %1, %2, %0;" : "+l"(acc) : "l"(a), "l"(b));
}
__device__ __forceinline__ unsigned long long pk2(float lo, float hi) {
    unsigned long long r;
    asm("mov.b64 %0, {%1, %2};" : "=l"(r) : "f"(lo), "f"(hi));
    return r;
}
__device__ __forceinline__ float upk_sum(unsigned long long v) {
    float lo, hi;
    asm("mov.b64 {%0, %1}, %2;" : "=f"(lo), "=f"(hi) : "l"(v));
    return lo + hi;
}

// Radial basis constants
#define RB_GAMMA 20.48f
#define RB_DELTA (5.0f / 31.0f)
#define RB_2GD 6.6064516129032258f
#define RB_GDD 0.5327783558792925

// Parameter rows in s_par
#define P_LNB 0
#define P_B2  1
#define P_BB  2
#define P_G0  3
#define P_G1  4
#define P_G2  5

// ============================================================================
// Kernel 1: per-atom B = A @ W1 (+ 0.5*b1 on scalar rows).
// ============================================================================
__global__ void __launch_bounds__(128) atom_dense_kernel(
    const float* __restrict__ A, const float* __restrict__ W1,
    const float* __restrict__ b1, int n_rows) {
    const int lane = threadIdx.x & 31;
    float wcol[32];
#pragma unroll
    for (int g = 0; g < 32; ++g) wcol[g] = W1[g * 32 + lane];
    const float hb1 = 0.5f * b1[lane];
    const int wid = (blockIdx.x * blockDim.x + threadIdx.x) >> 5;
    const int nw = (gridDim.x * blockDim.x) >> 5;
    for (int row = wid; row < n_rows; row += nw) {
        const float4* ar = (const float4*)(A + (size_t)row * 32);
        float acc = 0.f;
#pragma unroll
        for (int q = 0; q < 8; ++q) {
            float4 v = ar[q];
            acc = fmaf(v.x, wcol[4 * q + 0], acc);
            acc = fmaf(v.y, wcol[4 * q + 1], acc);
            acc = fmaf(v.z, wcol[4 * q + 2], acc);
            acc = fmaf(v.w, wcol[4 * q + 3], acc);
        }
        // fold half the dense-1 bias into every scalar-channel (m=0) row
        int m = row - (row / 9) * 9;
        if (m == 0) acc += hb1;
        g_B[(size_t)row * 32 + lane] = acc;
    }
}

// ============================================================================
// Kernel 2: fused per-edge pipeline. warp = edge, lane = feature.
// ============================================================================
__global__ void __launch_bounds__(128, 6) edge_kernel(
    const int* __restrict__ nbr, const float* __restrict__ disp,
    const float* __restrict__ lng,
    const float* __restrict__ lnb, const float* __restrict__ W2,
    const float* __restrict__ b2, const float* __restrict__ Wb,
    const float* __restrict__ bbv, const float* __restrict__ tpw_g,
    float* __restrict__ out, int E) {
    // Wb padded: rows -6..37 (index +6), zero rows outside [0,32)
    __shared__ __align__(16) float s_wbp[44 * 32];
    __shared__ __align__(16) float s_tpw[NPATHS * 32]; // tp_w[p][g]
    __shared__ __align__(16) float s_yg[4][9][32];     // per-warp gated features
    __shared__ __align__(16) float s_par[6 * 32];      // per-lane parameters

    const int lane = threadIdx.x & 31;
    const int wib = threadIdx.x >> 5;

    for (int x = threadIdx.x; x < 44 * 32; x += blockDim.x) {
        int row = (x >> 5) - 6;
        s_wbp[x] = (row >= 0 && row < 32) ? Wb[row * 32 + (x & 31)] : 0.f;
    }
    for (int x = threadIdx.x; x < NPATHS * 32; x += blockDim.x) s_tpw[x] = tpw_g[x];
    if (threadIdx.x < 32) {
        s_par[P_LNB * 32 + lane] = lnb[lane];
        s_par[P_B2  * 32 + lane] = b2[lane];
        s_par[P_BB  * 32 + lane] = bbv[lane];
        s_par[P_G0  * 32 + lane] = lng[lane];
        s_par[P_G1  * 32 + lane] = lng[32 + lane];
        s_par[P_G2  * 32 + lane] = lng[64 + lane];
    }
    __syncthreads();

    // W2 column for this lane, packed into f32x2 pairs (features 2k,2k+1)
    unsigned long long w2p[16];
#pragma unroll
    for (int k = 0; k < 16; ++k)
        w2p[k] = pk2(W2[(2 * k) * 32 + lane], W2[(2 * k + 1) * 32 + lane]);

    const int wid = (blockIdx.x * blockDim.x + threadIdx.x) >> 5;
    const int nw = (gridDim.x * blockDim.x) >> 5;
    const int2* __restrict__ nbr2 = (const int2*)nbr;

    for (int e = wid; e < E; e += nw) {
        const int2 ij = nbr2[e];

        // ---- y0 = B[i] + B[j] (b1 pre-folded into g_B) ----
        float y0[9];
#pragma unroll
        for (int m = 0; m < 9; ++m)
            y0[m] = g_B[((size_t)ij.x * 9 + m) * 32 + lane] +
                    g_B[((size_t)ij.y * 9 + m) * 32 + lane];

        // ---- equivariant layernorm ----
        float yg[9];
        {
            float s = y0[0];
            float mu = wsum(s) * (1.f / 32.f);
            float d = s - mu;
            float var = wsum(d * d) * (1.f / 32.f);
            yg[0] = d * rsqrtf(var + 1e-6f) * s_par[P_G0 * 32 + lane] +
                    s_par[P_LNB * 32 + lane];

            float ss1 = y0[1] * y0[1] + y0[2] * y0[2] + y0[3] * y0[3];
            float inv1 = s_par[P_G1 * 32 + lane] *
                         rsqrtf(wsum(ss1) * (1.f / 96.f) + 1e-6f);
            yg[1] = y0[1] * inv1; yg[2] = y0[2] * inv1; yg[3] = y0[3] * inv1;

            float ss2 = y0[4] * y0[4] + y0[5] * y0[5] + y0[6] * y0[6] +
                        y0[7] * y0[7] + y0[8] * y0[8];
            float inv2 = s_par[P_G2 * 32 + lane] *
                         rsqrtf(wsum(ss2) * (1.f / 160.f) + 1e-6f);
#pragma unroll
            for (int m = 4; m < 9; ++m) yg[m] = y0[m] * inv2;
        }

        // ---- mish gate (fast-math) ----
        {
            float s = yg[0];
            float ea = __expf(-fabsf(s));
            float sp = fmaxf(s, 0.f) + __logf(1.f + ea);
            float E2 = __expf(-2.f * sp);
            float th = __fdividef(1.f - E2, 1.f + E2);
            float i1 = __fdividef(1.f, 1.f + ea);
            float sig = (s >= 0.f) ? i1 : 1.f - i1;
            yg[0] = s * th;
            float dg = th + s * (1.f - th * th) * sig;
#pragma unroll
            for (int m = 1; m < 9; ++m) yg[m] *= dg;
        }

        // ---- stage yg to smem for broadcast dense2 ----
        __syncwarp();
#pragma unroll
        for (int m = 0; m < 9; ++m) s_yg[wib][m][lane] = yg[m];
        __syncwarp();

        // ---- bond geometry ----
        float dx = disp[3 * e], dy = disp[3 * e + 1], dz = disp[3 * e + 2];
        float r = sqrtf(dx * dx + dy * dy + dz * dz);
        float rinv = __fdividef(1.f, fmaxf(r, 1e-12f));
        float ux = dx * rinv, uy = dy * rinv, uz = dz * rinv;

        // ---- radW[g] via 13-tap geometric window ----
        float radW = 0.f;
        if (r < 5.f) {                                   // warp-uniform branch
            int kc = __float2int_rn(r * (31.0f / 5.0f));
            float t = r - (float)kc * RB_DELTA;          // |t| <= delta/2
            float rad_c = __expf(-RB_GAMMA * t * t);
            float beta = __expf(RB_2GD * t);
            float b2_ = beta * beta, b4 = b2_ * b2_;
            float bp = __fdividef(1.f, b4 * b2_);        // beta^-6
            float acc = 0.f;
            const float* wrow = s_wbp + (kc * 32 + lane);
            sfor<0, 13>([&](auto Dc) {
                constexpr int D = decltype(Dc)::v - 6;
                constexpr float H = (float)cexp_(-RB_GDD * (double)(D * D));
                acc = fmaf(bp * H, wrow[(D + 6) * 32], acc);
                bp *= beta;
            });
            float cut = 0.5f * (__cosf(r * 0.6283185307179586f) + 1.f);
            radW = rad_c * cut * acc;
        }

        const float s3 = 1.7320508075688772f;
        float av[9];
        av[0] = radW + s_par[P_BB * 32 + lane];
        av[1] = uy * radW; av[2] = uz * radW; av[3] = ux * radW;
        av[4] = s3 * ux * uy * radW;
        av[5] = s3 * uy * uz * radW;
        av[6] = 0.5f * (3.f * uz * uz - 1.f) * radW;
        av[7] = s3 * ux * uz * radW;
        av[8] = 0.5f * s3 * (ux * ux - uy * uy) * radW;

        // ---- dense2 via uniform LDS.128 + packed f32x2 FMA ----
        float y2[9];
        {
            const ulonglong2* yq = (const ulonglong2*)&s_yg[wib][0][0];
            sfor<0, 9>([&](auto M) {
                constexpr int m = decltype(M)::v;
                unsigned long long acc = 0ull;
#pragma unroll
                for (int q = 0; q < 8; ++q) {
                    ulonglong2 v = yq[m * 8 + q];   // yg[m][4q..4q+3]
                    ffma2(acc, v.x, w2p[2 * q]);
                    ffma2(acc, v.y, w2p[2 * q + 1]);
                }
                y2[m] = upk_sum(acc);
            });
        }
        y2[0] += s_par[P_B2 * 32 + lane];
#pragma unroll
        for (int m = 0; m < 9; ++m) y2[m] += y0[m];

        // ---- tensor product per (parity, l3) block; store immediately ----
        float* ob = out + (size_t)e * 1600 + lane;

        auto do_group = [&](auto PARc, auto L3c) {
            constexpr int PAR = decltype(PARc)::v;
            constexpr int L3 = decltype(L3c)::v;
            float acc[2 * L3 + 1];
#pragma unroll
            for (int c = 0; c < 2 * L3 + 1; ++c) acc[c] = 0.f;
            sfor<0, NPATHS>([&](auto P) {
                constexpr int p = decltype(P)::v;
                constexpr int l1 = PL1[p], l2 = PL2[p], l3 = PL3[p];
                constexpr int par = (l1 + l2 + l3) & 1;
                if constexpr (l3 == L3 && par == PAR) {
                    float tw = s_tpw[p * 32 + lane];
                    sfor<0, 2 * l1 + 1>([&](auto Ai) {
                        constexpr int aI = decltype(Ai)::v;
                        float ta = av[l1 * l1 + aI] * tw;
                        sfor<0, 2 * l2 + 1>([&](auto Bi) {
                            constexpr int bI = decltype(Bi)::v;
                            float t = ta * y2[l2 * l2 + bI];
                            sfor<0, 2 * l3 + 1>([&](auto Ci) {
                                constexpr int cI = decltype(Ci)::v;
                                constexpr float cf = (float)real_cg(l1, l2, l3, aI, bI, cI);
                                if constexpr (cf > 1e-7f || cf < -1e-7f)
                                    acc[cI] = fmaf(cf, t, acc[cI]);
                            });
                        });
                    });
                }
            });
            float* og = ob + (PAR * 25 + L3 * L3) * 32;
#pragma unroll
            for (int c = 0; c < 2 * L3 + 1; ++c) __stcs(og + c * 32, acc[c]);
        };

        do_group(IC<0>{}, IC<0>{});
        do_group(IC<0>{}, IC<1>{});
        do_group(IC<0>{}, IC<2>{});
        do_group(IC<0>{}, IC<3>{});
        do_group(IC<0>{}, IC<4>{});
        do_group(IC<1>{}, IC<1>{});
        do_group(IC<1>{}, IC<2>{});
        do_group(IC<1>{}, IC<3>{});

        // structurally-zero blocks: (par=1,l3=0) scalar + (par=1,l3=4) 9ch
        __stcs(ob + 25 * 32, 0.f);
        {
            // region floats [41*32, 50*32): 288 floats, lane-remapped float4
            float4* zb = (float4*)(out + (size_t)e * 1600 + 41 * 32);
            float4 z4 = make_float4(0.f, 0.f, 0.f, 0.f);
            __stcs(zb + lane, z4);
            __stcs(zb + 32 + lane, z4);
            if (lane < 8) __stcs(zb + 64 + lane, z4);
        }
    }
}

// ============================================================================
// Launch
// ============================================================================
extern "C" void kernel_launch(void* const* d_in, const int* in_sizes, int n_in,
                              void* d_out, int out_size) {
    const float* A    = (const float*)d_in[0];
    const int*   nbr  = (const int*)d_in[1];
    const float* disp = (const float*)d_in[2];
    const float* W1   = (const float*)d_in[3];
    const float* b1   = (const float*)d_in[4];
    const float* lng  = (const float*)d_in[5];
    const float* lnb  = (const float*)d_in[6];
    const float* W2   = (const float*)d_in[7];
    const float* b2   = (const float*)d_in[8];
    const float* Wb   = (const float*)d_in[9];
    const float* bb   = (const float*)d_in[10];
    const float* tpw  = (const float*)d_in[11];
    float* out = (float*)d_out;

    int n_atoms = in_sizes[0] / (9 * NFEAT);
    int E = in_sizes[1] / 2;

    atom_dense_kernel<<<592, 128>>>(A, W1, b1, n_atoms * 9);
    edge_kernel<<<888, 128>>>(nbr, disp, lng, lnb, W2, b2, Wb, bb, tpw, out, E);
    (void)n_in; (void)out_size;
}

// round 15
// speedup vs baseline: 1.0422x; 1.0422x over previous
#include <cuda_runtime.h>

// ============================================================================
// Problem constants
// ============================================================================
#define NFEAT 32
#define MAX_ATOMS 10000
#define NPATHS 19

// Scratch: per-atom B = A @ W1 (+0.5*b1 on m=0 rows)
__device__ float g_B[MAX_ATOMS * 9 * NFEAT];

// ============================================================================
// constexpr math (compile-time): factorial, sqrt, exp
// ============================================================================
__host__ __device__ constexpr double cfact(int n) {
    double r = 1.0;
    for (int i = 2; i <= n; ++i) r *= (double)i;
    return r;
}
__host__ __device__ constexpr double csqrt_(double x) {
    if (x <= 0.0) return 0.0;
    double g = x < 1.0 ? 1.0 : x;
    for (int i = 0; i < 80; ++i) g = 0.5 * (g + x / g);
    return g;
}
__host__ __device__ constexpr double cexp_(double x) {
    double y = x * (1.0 / 1024.0);
    double s = 1.0 + y + y * y / 2.0 + y * y * y / 6.0 + y * y * y * y / 24.0 +
               y * y * y * y * y / 120.0 + y * y * y * y * y * y / 720.0;
    for (int i = 0; i < 10; ++i) s = s * s;
    return s;
}
__host__ __device__ constexpr int iabs_(int x) { return x < 0 ? -x : x; }

// ============================================================================
// constexpr Clebsch-Gordan machinery — bit-faithful port of the reference
// ============================================================================
__host__ __device__ constexpr double cg_c(int j1, int m1, int j2, int m2, int j3, int m3) {
    if (m1 + m2 != m3) return 0.0;
    if (j3 < iabs_(j1 - j2) || j3 > j1 + j2) return 0.0;
    if (iabs_(m1) > j1 || iabs_(m2) > j2 || iabs_(m3) > j3) return 0.0;
    double pref = csqrt_((2.0 * j3 + 1.0) * cfact(j3 + j1 - j2) * cfact(j3 - j1 + j2) *
                         cfact(j1 + j2 - j3) / cfact(j1 + j2 + j3 + 1));
    pref *= csqrt_(cfact(j3 + m3) * cfact(j3 - m3) * cfact(j1 - m1) * cfact(j1 + m1) *
                   cfact(j2 - m2) * cfact(j2 + m2));
    double s = 0.0;
    for (int k = 0; k <= j1 + j2 - j3; ++k) {
        int d1 = j1 + j2 - j3 - k, d2 = j1 - m1 - k, d3 = j2 + m2 - k;
        int d4 = j3 - j2 + m1 + k, d5 = j3 - j1 - m2 + k;
        if (d1 < 0 || d2 < 0 || d3 < 0 || d4 < 0 || d5 < 0) continue;
        double den = cfact(k) * cfact(d1) * cfact(d2) * cfact(d3) * cfact(d4) * cfact(d5);
        s += ((k & 1) ? -1.0 : 1.0) / den;
    }
    return pref * s;
}

struct CPX { double re, im; };
__host__ __device__ constexpr CPX cmulc(CPX a, CPX b) {
    return CPX{a.re * b.re - a.im * b.im, a.re * b.im + a.im * b.re};
}
__host__ __device__ constexpr CPX Uent(int l, int mr, int mc) {
    (void)l;
    double is2 = 1.0 / csqrt_(2.0);
    if (mr > 0) {
        if (mc == mr)  return CPX{((mr & 1) ? -1.0 : 1.0) * is2, 0.0};
        if (mc == -mr) return CPX{is2, 0.0};
    } else if (mr == 0) {
        if (mc == 0) return CPX{1.0, 0.0};
    } else {
        int mu = -mr;
        if (mc == mr) return CPX{0.0, is2};
        if (mc == mu) return CPX{0.0, -((mu & 1) ? -1.0 : 1.0) * is2};
    }
    return CPX{0.0, 0.0};
}

__host__ __device__ constexpr double real_cg(int l1, int l2, int l3, int a, int b, int c) {
    int m1 = a - l1, m2 = b - l2, m3 = c - l3;
    double re = 0.0, im = 0.0;
    for (int sx = 0; sx < 2; ++sx) {
        if (sx && m1 == 0) continue;
        int x = sx ? -m1 : m1;
        CPX u1 = Uent(l1, m1, x); u1.im = -u1.im;
        for (int sy = 0; sy < 2; ++sy) {
            if (sy && m2 == 0) continue;
            int y = sy ? -m2 : m2;
            CPX u2 = Uent(l2, m2, y); u2.im = -u2.im;
            for (int sz = 0; sz < 2; ++sz) {
                if (sz && m3 == 0) continue;
                int z = sz ? -m3 : m3;
                CPX u3 = Uent(l3, m3, z);
                double cg = cg_c(l1, x, l2, y, l3, z);
                if (cg == 0.0) continue;
                CPX t = cmulc(cmulc(u1, u2), u3);
                re += t.re * cg;
                im += t.im * cg;
            }
        }
    }
    return ((l1 + l2 + l3) & 1) ? im : re;
}

// Path table, same enumeration order as reference _build_paths()
__host__ __device__ constexpr int PL1[NPATHS] = {0,0,0,1,1,1,1,1,1,1,2,2,2,2,2,2,2,2,2};
__host__ __device__ constexpr int PL2[NPATHS] = {0,1,2,0,1,1,1,2,2,2,0,1,1,1,2,2,2,2,2};
__host__ __device__ constexpr int PL3[NPATHS] = {0,1,2,1,0,1,2,1,2,3,2,1,2,3,0,1,2,3,4};

template <int I> struct IC { static constexpr int v = I; };
template <int I, int N, class F>
__device__ __forceinline__ void sfor(F&& f) {
    if constexpr (I < N) {
        f(IC<I>{});
        sfor<I + 1, N>(f);
    }
}

__device__ __forceinline__ float wsum(float v) {
    v += __shfl_xor_sync(0xffffffffu, v, 16);
    v += __shfl_xor_sync(0xffffffffu, v, 8);
    v += __shfl_xor_sync(0xffffffffu, v, 4);
    v += __shfl_xor_sync(0xffffffffu, v, 2);
    v += __shfl_xor_sync(0xffffffffu, v, 1);
    return v;
}

// packed f32x2 fma (sm_103): acc = a*b + acc, lanes independent
__device__ __forceinline__ void ffma2(unsigned long long& acc,
                                      unsigned long long a, unsigned long long b) {
    asm("fma.rn.f32x2 %0, %1, %2, %0;" : "+l"(acc) : "l"(a), "l"(b));
}
__device__ __forceinline__ unsigned long long pk2(float lo, float hi) {
    unsigned long long r;
    asm("mov.b64 %0, {%1, %2};" : "=l"(r) : "f"(lo), "f"(hi));
    return r;
}
__device__ __forceinline__ float upk_sum(unsigned long long v) {
    float lo, hi;
    asm("mov.b64 {%0, %1}, %2;" : "=f"(lo), "=f"(hi) : "l"(v));
    return lo + hi;
}

// Radial basis constants
#define RB_GAMMA 20.48f
#define RB_DELTA (5.0f / 31.0f)
#define RB_2GD 6.6064516129032258f
#define RB_GDD 0.5327783558792925

// Parameter rows in s_par
#define P_LNB 0
#define P_B2  1
#define P_BB  2
#define P_G0  3
#define P_G1  4
#define P_G2  5

// ============================================================================
// Kernel 1: per-atom B = A @ W1 (+ 0.5*b1 on scalar rows).
// ============================================================================
__global__ void __launch_bounds__(128) atom_dense_kernel(
    const float* __restrict__ A, const float* __restrict__ W1,
    const float* __restrict__ b1, int n_rows) {
    const int lane = threadIdx.x & 31;
    float wcol[32];
#pragma unroll
    for (int g = 0; g < 32; ++g) wcol[g] = W1[g * 32 + lane];
    const float hb1 = 0.5f * b1[lane];
    const int wid = (blockIdx.x * blockDim.x + threadIdx.x) >> 5;
    const int nw = (gridDim.x * blockDim.x) >> 5;
    for (int row = wid; row < n_rows; row += nw) {
        const float4* ar = (const float4*)(A + (size_t)row * 32);
        float acc = 0.f;
#pragma unroll
        for (int q = 0; q < 8; ++q) {
            float4 v = ar[q];
            acc = fmaf(v.x, wcol[4 * q + 0], acc);
            acc = fmaf(v.y, wcol[4 * q + 1], acc);
            acc = fmaf(v.z, wcol[4 * q + 2], acc);
            acc = fmaf(v.w, wcol[4 * q + 3], acc);
        }
        int m = row - (row / 9) * 9;
        if (m == 0) acc += hb1;
        g_B[(size_t)row * 32 + lane] = acc;
    }
}

// ============================================================================
// Kernel 2: fused per-edge pipeline. warp = edge, lane = feature.
// Software-pipelined: next edge's (ij, disp, y0) prefetched during TP/stores.
// ============================================================================
__global__ void __launch_bounds__(128, 5) edge_kernel(
    const int* __restrict__ nbr, const float* __restrict__ disp,
    const float* __restrict__ lng,
    const float* __restrict__ lnb, const float* __restrict__ W2,
    const float* __restrict__ b2, const float* __restrict__ Wb,
    const float* __restrict__ bbv, const float* __restrict__ tpw_g,
    float* __restrict__ out, int E) {
    // Wb padded: rows -5..36 (index +5), zero rows outside [0,32)
    __shared__ __align__(16) float s_wbp[42 * 32];
    __shared__ __align__(16) float s_tpw[NPATHS * 32]; // tp_w[p][g]
    __shared__ __align__(16) float s_yg[4][9][32];     // per-warp gated features
    __shared__ __align__(16) float s_par[6 * 32];      // per-lane parameters

    const int lane = threadIdx.x & 31;
    const int wib = threadIdx.x >> 5;

    for (int x = threadIdx.x; x < 42 * 32; x += blockDim.x) {
        int row = (x >> 5) - 5;
        s_wbp[x] = (row >= 0 && row < 32) ? Wb[row * 32 + (x & 31)] : 0.f;
    }
    for (int x = threadIdx.x; x < NPATHS * 32; x += blockDim.x) s_tpw[x] = tpw_g[x];
    if (threadIdx.x < 32) {
        s_par[P_LNB * 32 + lane] = lnb[lane];
        s_par[P_B2  * 32 + lane] = b2[lane];
        s_par[P_BB  * 32 + lane] = bbv[lane];
        s_par[P_G0  * 32 + lane] = lng[lane];
        s_par[P_G1  * 32 + lane] = lng[32 + lane];
        s_par[P_G2  * 32 + lane] = lng[64 + lane];
    }
    __syncthreads();

    // W2 column for this lane, packed into f32x2 pairs (features 2k,2k+1)
    unsigned long long w2p[16];
#pragma unroll
    for (int k = 0; k < 16; ++k)
        w2p[k] = pk2(W2[(2 * k) * 32 + lane], W2[(2 * k + 1) * 32 + lane]);

    const int wid = (blockIdx.x * blockDim.x + threadIdx.x) >> 5;
    const int nw = (gridDim.x * blockDim.x) >> 5;
    const int2* __restrict__ nbr2 = (const int2*)nbr;

    if (wid >= E) return;

    // ---- prologue: load edge `wid` state ----
    float y0[9];
    float dx, dy, dz;
    {
        int2 ij = nbr2[wid];
#pragma unroll
        for (int m = 0; m < 9; ++m)
            y0[m] = g_B[((size_t)ij.x * 9 + m) * 32 + lane] +
                    g_B[((size_t)ij.y * 9 + m) * 32 + lane];
        dx = disp[3 * wid]; dy = disp[3 * wid + 1]; dz = disp[3 * wid + 2];
    }

    for (int e = wid; e < E; e += nw) {
        // ---- equivariant layernorm ----
        float yg[9];
        {
            float s = y0[0];
            float mu = wsum(s) * (1.f / 32.f);
            float d = s - mu;
            float var = wsum(d * d) * (1.f / 32.f);
            yg[0] = d * rsqrtf(var + 1e-6f) * s_par[P_G0 * 32 + lane] +
                    s_par[P_LNB * 32 + lane];

            float ss1 = y0[1] * y0[1] + y0[2] * y0[2] + y0[3] * y0[3];
            float inv1 = s_par[P_G1 * 32 + lane] *
                         rsqrtf(wsum(ss1) * (1.f / 96.f) + 1e-6f);
            yg[1] = y0[1] * inv1; yg[2] = y0[2] * inv1; yg[3] = y0[3] * inv1;

            float ss2 = y0[4] * y0[4] + y0[5] * y0[5] + y0[6] * y0[6] +
                        y0[7] * y0[7] + y0[8] * y0[8];
            float inv2 = s_par[P_G2 * 32 + lane] *
                         rsqrtf(wsum(ss2) * (1.f / 160.f) + 1e-6f);
#pragma unroll
            for (int m = 4; m < 9; ++m) yg[m] = y0[m] * inv2;
        }

        // ---- mish gate (fast-math) ----
        {
            float s = yg[0];
            float ea = __expf(-fabsf(s));
            float sp = fmaxf(s, 0.f) + __logf(1.f + ea);
            float E2 = __expf(-2.f * sp);
            float th = __fdividef(1.f - E2, 1.f + E2);
            float i1 = __fdividef(1.f, 1.f + ea);
            float sig = (s >= 0.f) ? i1 : 1.f - i1;
            yg[0] = s * th;
            float dg = th + s * (1.f - th * th) * sig;
#pragma unroll
            for (int m = 1; m < 9; ++m) yg[m] *= dg;
        }

        // ---- stage yg to smem for broadcast dense2 ----
        __syncwarp();
#pragma unroll
        for (int m = 0; m < 9; ++m) s_yg[wib][m][lane] = yg[m];
        __syncwarp();

        // ---- bond geometry (disp prefetched last iteration) ----
        float r = sqrtf(dx * dx + dy * dy + dz * dz);
        float rinv = __fdividef(1.f, fmaxf(r, 1e-12f));
        float ux = dx * rinv, uy = dy * rinv, uz = dz * rinv;

        // ---- radW[g] via 11-tap geometric window ----
        float radW = 0.f;
        if (r < 5.f) {                                   // warp-uniform branch
            int kc = __float2int_rn(r * (31.0f / 5.0f));
            float t = r - (float)kc * RB_DELTA;          // |t| <= delta/2
            float rad_c = __expf(-RB_GAMMA * t * t);
            float beta = __expf(RB_2GD * t);
            float b2_ = beta * beta, b4 = b2_ * b2_;
            float bp = __fdividef(1.f, b4 * beta);       // beta^-5
            float acc = 0.f;
            const float* wrow = s_wbp + (kc * 32 + lane);
            sfor<0, 11>([&](auto Dc) {
                constexpr int D = decltype(Dc)::v - 5;
                constexpr float H = (float)cexp_(-RB_GDD * (double)(D * D));
                acc = fmaf(bp * H, wrow[(D + 5) * 32], acc);
                bp *= beta;
            });
            float cut = 0.5f * (__cosf(r * 0.6283185307179586f) + 1.f);
            radW = rad_c * cut * acc;
        }

        const float s3 = 1.7320508075688772f;
        float av[9];
        av[0] = radW + s_par[P_BB * 32 + lane];
        av[1] = uy * radW; av[2] = uz * radW; av[3] = ux * radW;
        av[4] = s3 * ux * uy * radW;
        av[5] = s3 * uy * uz * radW;
        av[6] = 0.5f * (3.f * uz * uz - 1.f) * radW;
        av[7] = s3 * ux * uz * radW;
        av[8] = 0.5f * s3 * (ux * ux - uy * uy) * radW;

        // ---- dense2 via uniform LDS.128 + packed f32x2 FMA ----
        float y2[9];
        {
            const ulonglong2* yq = (const ulonglong2*)&s_yg[wib][0][0];
            sfor<0, 9>([&](auto M) {
                constexpr int m = decltype(M)::v;
                unsigned long long acc = 0ull;
#pragma unroll
                for (int q = 0; q < 8; ++q) {
                    ulonglong2 v = yq[m * 8 + q];   // yg[m][4q..4q+3]
                    ffma2(acc, v.x, w2p[2 * q]);
                    ffma2(acc, v.y, w2p[2 * q + 1]);
                }
                y2[m] = upk_sum(acc);
            });
        }
        y2[0] += s_par[P_B2 * 32 + lane];
#pragma unroll
        for (int m = 0; m < 9; ++m) y2[m] += y0[m];

        // ---- prefetch next edge into the (now dead) y0 registers ----
        {
            int en = e + nw;
            if (en < E) {
                int2 ij = nbr2[en];
#pragma unroll
                for (int m = 0; m < 9; ++m)
                    y0[m] = g_B[((size_t)ij.x * 9 + m) * 32 + lane] +
                            g_B[((size_t)ij.y * 9 + m) * 32 + lane];
                dx = disp[3 * en]; dy = disp[3 * en + 1]; dz = disp[3 * en + 2];
            }
        }

        // ---- tensor product per (parity, l3) block; store immediately ----
        float* ob = out + (size_t)e * 1600 + lane;

        auto do_group = [&](auto PARc, auto L3c) {
            constexpr int PAR = decltype(PARc)::v;
            constexpr int L3 = decltype(L3c)::v;
            float acc[2 * L3 + 1];
#pragma unroll
            for (int c = 0; c < 2 * L3 + 1; ++c) acc[c] = 0.f;
            sfor<0, NPATHS>([&](auto P) {
                constexpr int p = decltype(P)::v;
                constexpr int l1 = PL1[p], l2 = PL2[p], l3 = PL3[p];
                constexpr int par = (l1 + l2 + l3) & 1;
                if constexpr (l3 == L3 && par == PAR) {
                    float tw = s_tpw[p * 32 + lane];
                    sfor<0, 2 * l1 + 1>([&](auto Ai) {
                        constexpr int aI = decltype(Ai)::v;
                        float ta = av[l1 * l1 + aI] * tw;
                        sfor<0, 2 * l2 + 1>([&](auto Bi) {
                            constexpr int bI = decltype(Bi)::v;
                            float t = ta * y2[l2 * l2 + bI];
                            sfor<0, 2 * l3 + 1>([&](auto Ci) {
                                constexpr int cI = decltype(Ci)::v;
                                constexpr float cf = (float)real_cg(l1, l2, l3, aI, bI, cI);
                                if constexpr (cf > 1e-7f || cf < -1e-7f)
                                    acc[cI] = fmaf(cf, t, acc[cI]);
                            });
                        });
                    });
                }
            });
            float* og = ob + (PAR * 25 + L3 * L3) * 32;
#pragma unroll
            for (int c = 0; c < 2 * L3 + 1; ++c) __stcs(og + c * 32, acc[c]);
        };

        do_group(IC<0>{}, IC<0>{});
        do_group(IC<0>{}, IC<1>{});
        do_group(IC<0>{}, IC<2>{});
        do_group(IC<0>{}, IC<3>{});
        do_group(IC<0>{}, IC<4>{});
        do_group(IC<1>{}, IC<1>{});
        do_group(IC<1>{}, IC<2>{});
        do_group(IC<1>{}, IC<3>{});

        // structurally-zero blocks: (par=1,l3=0) scalar + (par=1,l3=4) 9ch
        __stcs(ob + 25 * 32, 0.f);
        {
            // region floats [41*32, 50*32): 288 floats, lane-remapped float4
            float4* zb = (float4*)(out + (size_t)e * 1600 + 41 * 32);
            float4 z4 = make_float4(0.f, 0.f, 0.f, 0.f);
            __stcs(zb + lane, z4);
            __stcs(zb + 32 + lane, z4);
            if (lane < 8) __stcs(zb + 64 + lane, z4);
        }
    }
}

// ============================================================================
// Launch
// ============================================================================
extern "C" void kernel_launch(void* const* d_in, const int* in_sizes, int n_in,
                              void* d_out, int out_size) {
    const float* A    = (const float*)d_in[0];
    const int*   nbr  = (const int*)d_in[1];
    const float* disp = (const float*)d_in[2];
    const float* W1   = (const float*)d_in[3];
    const float* b1   = (const float*)d_in[4];
    const float* lng  = (const float*)d_in[5];
    const float* lnb  = (const float*)d_in[6];
    const float* W2   = (const float*)d_in[7];
    const float* b2   = (const float*)d_in[8];
    const float* Wb   = (const float*)d_in[9];
    const float* bb   = (const float*)d_in[10];
    const float* tpw  = (const float*)d_in[11];
    float* out = (float*)d_out;

    int n_atoms = in_sizes[0] / (9 * NFEAT);
    int E = in_sizes[1] / 2;

    atom_dense_kernel<<<592, 128>>>(A, W1, b1, n_atoms * 9);
    edge_kernel<<<740, 128>>>(nbr, disp, lng, lnb, W2, b2, Wb, bb, tpw, out, E);
    (void)n_in; (void)out_size;
}